// round 3
// baseline (speedup 1.0000x reference)
#include <cuda_runtime.h>
#include <cstdint>

// ---------------- problem constants ----------------
#define CC      64
#define HH      120
#define WW      120
#define NBOX    8192
#define HID     128
#define SCOORD  (119.0f / 960.0f)

#define FIN_A   576
#define FIN_B   3136
#define FIN_C   7744
#define FIN_TOT (FIN_A + FIN_B + FIN_C)

// ---------------- device scratch ----------------
__device__ float d_fmT[HH * WW * CC];          // [y][x][c]
__device__ float d_W1T[FIN_TOT * HID];         // pos-major permuted W1^T
__device__ float d_gf[CC];
__device__ float d_g[16];

// ---------------- f32x2 / cp.async helpers ----------------
__device__ __forceinline__ unsigned long long pack2(float x) {
    unsigned long long r;
    asm("mov.b64 %0, {%1, %1};" : "=l"(r) : "r"(__float_as_uint(x)));
    return r;
}
__device__ __forceinline__ void fma2(unsigned long long& d,
                                     unsigned long long a,
                                     unsigned long long b) {
    asm("fma.rn.f32x2 %0, %1, %2, %0;" : "+l"(d) : "l"(a), "l"(b));
}
__device__ __forceinline__ uint32_t smem_u32(const void* p) {
    uint32_t a;
    asm("{ .reg .u64 t; cvta.to.shared.u64 t, %1; cvt.u32.u64 %0, t; }" : "=r"(a) : "l"(p));
    return a;
}
__device__ __forceinline__ void cp_async16(uint32_t s, const void* g) {
    asm volatile("cp.async.cg.shared.global [%0], [%1], 16;" :: "r"(s), "l"(g));
}
#define CP_COMMIT()  asm volatile("cp.async.commit_group;")
#define CP_WAIT0()   asm volatile("cp.async.wait_group 0;" ::: "memory")

// ---------------- prep kernels ----------------
__global__ void transpose_fm_kernel(const float* __restrict__ fm) {
    int idx = blockIdx.x * 256 + threadIdx.x;
    int c = idx & 63;
    int p = idx >> 6;
    d_fmT[idx] = fm[c * (HH * WW) + p];
}

// all three W1 transposes in one launch
__global__ void transpose_w1_all(const float* __restrict__ W1a,
                                 const float* __restrict__ W1b,
                                 const float* __restrict__ W1c) {
    int idx = blockIdx.x * 256 + threadIdx.x;
    const float* W1;
    int fin, r2, base;
    if (idx < FIN_A * HID)                { W1 = W1a; fin = FIN_A; r2 = 9;   base = 0; }
    else if (idx < (FIN_A + FIN_B) * HID) { W1 = W1b; fin = FIN_B; r2 = 49;  base = FIN_A * HID; }
    else if (idx < FIN_TOT * HID)         { W1 = W1c; fin = FIN_C; r2 = 121; base = (FIN_A + FIN_B) * HID; }
    else return;
    int rel = idx - base;
    int n   = rel & 127;
    int kp  = rel >> 7;
    int c   = kp & 63;
    int pos = kp >> 6;
    d_W1T[idx] = W1[n * fin + c * r2 + pos];
}

__global__ void gf_kernel(const float* __restrict__ fm) {
    int c = blockIdx.x;
    float s = 0.0f;
    for (int i = threadIdx.x; i < HH * WW; i += 256) s += fm[c * (HH * WW) + i];
    __shared__ float red[8];
    #pragma unroll
    for (int off = 16; off; off >>= 1) s += __shfl_down_sync(0xffffffffu, s, off);
    if ((threadIdx.x & 31) == 0) red[threadIdx.x >> 5] = s;
    __syncthreads();
    if (threadIdx.x < 8) {
        s = red[threadIdx.x];
        #pragma unroll
        for (int off = 4; off; off >>= 1) s += __shfl_down_sync(0xffu, s, off);
        if (threadIdx.x == 0) d_gf[c] = s / (float)(HH * WW);
    }
}

__global__ void g_kernel(const float* __restrict__ Wg, const float* __restrict__ bg) {
    int j = threadIdx.x;
    float s = bg[j];
    #pragma unroll 8
    for (int c = 0; c < CC; c++) s += d_gf[c] * Wg[j * CC + c];
    d_g[j] = s;
}

__global__ void g_write_kernel(float* __restrict__ out) {
    int idx = blockIdx.x * 256 + threadIdx.x;
    int m = idx >> 4;
    int j = idx & 15;
    out[m * 64 + 48 + j] = d_g[j];
}

// ---------------- unified fused head kernel ----------------
// 256 threads. CTA tile 64 boxes x 128 hidden, thread tile 4m x 8n.
// K-tile = 16. Double-buffered As/Bs, one syncthreads per K-tile.
// B tile via cp.async; A tile via register-prefetched gathers.

struct Pref {
    float4 t00, t01, t10, t11;
    float  w00, w01, w10, w11;
};

__device__ __forceinline__ Pref do_prefetch(int kt, int r, float invr,
                                            const float* __restrict__ boxp,
                                            int tid) {
    Pref p;
    int pos = kt >> 2;                 // 4 tiles of 16 channels per position
    int c0  = (kt & 3) << 4;
    int py  = pos / r;
    int px  = pos - py * r;
    float tx = px * invr;
    float ty = py * invr;

    int m    = tid >> 2;
    int cvec = c0 + ((tid & 3) << 2);

    const float4 bp = *reinterpret_cast<const float4*>(&boxp[m * 4]);
    float ix = fmaf(bp.y, tx, bp.x);
    float iy = fmaf(bp.w, ty, bp.z);
    float x0f = floorf(ix), y0f = floorf(iy);
    float wx = ix - x0f, wy = iy - y0f;
    int x0 = (int)x0f, y0 = (int)y0f;
    int x1 = x0 + 1,   y1 = y0 + 1;
    float vx0 = (x0 >= 0 && x0 < WW) ? 1.0f : 0.0f;
    float vx1 = (x1 >= 0 && x1 < WW) ? 1.0f : 0.0f;
    float vy0 = (y0 >= 0 && y0 < HH) ? 1.0f : 0.0f;
    float vy1 = (y1 >= 0 && y1 < HH) ? 1.0f : 0.0f;
    p.w00 = (1.0f - wx) * (1.0f - wy) * vx0 * vy0;
    p.w01 = wx * (1.0f - wy) * vx1 * vy0;
    p.w10 = (1.0f - wx) * wy * vx0 * vy1;
    p.w11 = wx * wy * vx1 * vy1;
    int cx0 = min(max(x0, 0), WW - 1), cx1 = min(max(x1, 0), WW - 1);
    int cy0 = min(max(y0, 0), HH - 1), cy1 = min(max(y1, 0), HH - 1);

    const float4* f = reinterpret_cast<const float4*>(d_fmT);
    int cq = cvec >> 2;
    p.t00 = __ldg(&f[(cy0 * WW + cx0) * 16 + cq]);
    p.t01 = __ldg(&f[(cy0 * WW + cx1) * 16 + cq]);
    p.t10 = __ldg(&f[(cy1 * WW + cx0) * 16 + cq]);
    p.t11 = __ldg(&f[(cy1 * WW + cx1) * 16 + cq]);
    return p;
}

__global__ void __launch_bounds__(256, 2)
unified_head_kernel(const float* __restrict__ boxes,
                    const float* __restrict__ b1a, const float* __restrict__ W2a,
                    const float* __restrict__ b2a,
                    const float* __restrict__ b1b, const float* __restrict__ W2b,
                    const float* __restrict__ b2b,
                    const float* __restrict__ b1c, const float* __restrict__ W2c,
                    const float* __restrict__ b2c,
                    const float* __restrict__ scale_w,
                    float* __restrict__ out) {
    // pool layout phase1: buf0 As[0,1024) Bs[1024,3072); buf1 As[3072,4096) Bs[4096,6144)
    //             phase2: Hs[0,8192)
    __shared__ float pool[8192];
    __shared__ float boxp[256];

    const int tid = threadIdx.x;
    const int bid = blockIdx.x;

    const float *b1, *W2, *b2;
    int fin, r, od, col0, swi, w1tbase;
    float invr;
    if (bid < 128) {
        b1 = b1c; W2 = W2c; b2 = b2c;
        fin = FIN_C; r = 11; invr = 0.1f; od = 5;  col0 = 43; swi = 2;
        w1tbase = (FIN_A + FIN_B) * HID;
    } else if (bid < 256) {
        b1 = b1b; W2 = W2b; b2 = b2b;
        fin = FIN_B; r = 7;  invr = 1.0f / 6.0f; od = 21; col0 = 22; swi = 1;
        w1tbase = FIN_A * HID;
    } else {
        b1 = b1a; W2 = W2a; b2 = b2a;
        fin = FIN_A; r = 3;  invr = 0.5f; od = 22; col0 = 0;  swi = 0;
        w1tbase = 0;
    }
    const int box0 = (bid & 127) * 64;

    if (tid < 64) {
        float4 b4 = __ldg(reinterpret_cast<const float4*>(boxes) + (box0 + tid));
        float4 o;
        o.x = b4.x * SCOORD;
        o.y = (b4.z - b4.x) * SCOORD;
        o.z = b4.y * SCOORD;
        o.w = (b4.w - b4.y) * SCOORD;
        *reinterpret_cast<float4*>(&boxp[tid * 4]) = o;
    }
    __syncthreads();

    const float* w1t = d_W1T + w1tbase;
    const int ntiles = fin >> 4;

    const int m0 = (tid >> 4) << 2;   // gemm: 4 boxes
    const int n0 = (tid & 15) << 3;   // gemm: 8 hidden
    const int sm  = tid >> 2;         // im2col: box
    const int skl = (tid & 3) << 2;   // im2col: channel group

    const uint32_t bs_base0 = smem_u32(&pool[1024]) + tid * 16;   // buf0 Bs
    const uint32_t bs_base1 = smem_u32(&pool[4096]) + tid * 16;   // buf1 Bs

    unsigned long long acc[4][4];
    #pragma unroll
    for (int i = 0; i < 4; i++)
        #pragma unroll
        for (int j = 0; j < 4; j++) acc[i][j] = 0ull;

    // prologue: B(0) via cp.async, A(0) taps to regs
    cp_async16(bs_base0,        w1t + tid * 4);
    cp_async16(bs_base0 + 4096, w1t + 1024 + tid * 4);
    CP_COMMIT();
    Pref p = do_prefetch(0, r, invr, boxp, tid);

    for (int kt = 0; kt < ntiles; ++kt) {
        float* As = pool + (kt & 1) * 3072;
        const float* Bs = As + 1024;

        // combine taps -> A tile [k][64]
        {
            float4 v;
            v.x = p.w00 * p.t00.x + p.w01 * p.t01.x + p.w10 * p.t10.x + p.w11 * p.t11.x;
            v.y = p.w00 * p.t00.y + p.w01 * p.t01.y + p.w10 * p.t10.y + p.w11 * p.t11.y;
            v.z = p.w00 * p.t00.z + p.w01 * p.t01.z + p.w10 * p.t10.z + p.w11 * p.t11.z;
            v.w = p.w00 * p.t00.w + p.w01 * p.t01.w + p.w10 * p.t10.w + p.w11 * p.t11.w;
            As[(skl + 0) * 64 + sm] = v.x;
            As[(skl + 1) * 64 + sm] = v.y;
            As[(skl + 2) * 64 + sm] = v.z;
            As[(skl + 3) * 64 + sm] = v.w;
        }

        // prefetch next A taps (hides gather latency under wait+sync+mma)
        if (kt + 1 < ntiles) p = do_prefetch(kt + 1, r, invr, boxp, tid);

        CP_WAIT0();          // B(kt) landed (this thread's copies)
        __syncthreads();     // all threads' A stores + B copies visible

        // issue B(kt+1) AFTER the barrier: nobody reads Bs[(kt+1)&1] anymore
        if (kt + 1 < ntiles) {
            uint32_t dstb = ((kt + 1) & 1) ? bs_base1 : bs_base0;
            const float* src = w1t + (size_t)(kt + 1) * 2048 + tid * 4;
            cp_async16(dstb,        src);
            cp_async16(dstb + 4096, src + 1024);
        }
        CP_COMMIT();

        #pragma unroll
        for (int k = 0; k < 16; k++) {
            float4 av = *reinterpret_cast<const float4*>(&As[k * 64 + m0]);
            ulonglong2 bv0 = *reinterpret_cast<const ulonglong2*>(&Bs[k * 128 + n0]);
            ulonglong2 bv1 = *reinterpret_cast<const ulonglong2*>(&Bs[k * 128 + n0 + 4]);
            unsigned long long a;
            a = pack2(av.x);
            fma2(acc[0][0], a, bv0.x); fma2(acc[0][1], a, bv0.y);
            fma2(acc[0][2], a, bv1.x); fma2(acc[0][3], a, bv1.y);
            a = pack2(av.y);
            fma2(acc[1][0], a, bv0.x); fma2(acc[1][1], a, bv0.y);
            fma2(acc[1][2], a, bv1.x); fma2(acc[1][3], a, bv1.y);
            a = pack2(av.z);
            fma2(acc[2][0], a, bv0.x); fma2(acc[2][1], a, bv0.y);
            fma2(acc[2][2], a, bv1.x); fma2(acc[2][3], a, bv1.y);
            a = pack2(av.w);
            fma2(acc[3][0], a, bv0.x); fma2(acc[3][1], a, bv0.y);
            fma2(acc[3][2], a, bv1.x); fma2(acc[3][3], a, bv1.y);
        }
        __syncthreads();     // MMA(kt) done before next iter overwrites As buf / final Hs
    }

    // layer-1 bias + relu -> Hs[64][128] (pool reuse; safe: sync above)
    float* Hs = pool;
    float b1v[8];
    #pragma unroll
    for (int j = 0; j < 8; j++) b1v[j] = __ldg(&b1[n0 + j]);
    #pragma unroll
    for (int i = 0; i < 4; i++) {
        #pragma unroll
        for (int j = 0; j < 4; j++) {
            unsigned long long v = acc[i][j];
            float f0 = __uint_as_float((unsigned int)v)         + b1v[2 * j];
            float f1 = __uint_as_float((unsigned int)(v >> 32)) + b1v[2 * j + 1];
            Hs[(m0 + i) * 128 + n0 + 2 * j]     = fmaxf(f0, 0.0f);
            Hs[(m0 + i) * 128 + n0 + 2 * j + 1] = fmaxf(f1, 0.0f);
        }
    }
    __syncthreads();

    // layer-2
    const float sw = __ldg(&scale_w[swi]);
    const int njobs = od << 6;
    for (int job = tid; job < njobs; job += 256) {
        int mm = job / od;
        int o  = job - mm * od;
        float s = __ldg(&b2[o]);
        const float4* hrow = reinterpret_cast<const float4*>(&Hs[mm * 128]);
        const float4* wrow = reinterpret_cast<const float4*>(&W2[o * 128]);
        #pragma unroll 8
        for (int qq = 0; qq < 32; qq++) {
            float4 h4 = hrow[qq];
            float4 w4 = __ldg(&wrow[qq]);
            s += h4.x * w4.x + h4.y * w4.y + h4.z * w4.z + h4.w * w4.w;
        }
        out[(size_t)(box0 + mm) * 64 + col0 + o] = fmaxf(s, 0.0f) * sw;
    }
}

// ---------------- launch ----------------
extern "C" void kernel_launch(void* const* d_in, const int* in_sizes, int n_in,
                              void* d_out, int out_size) {
    const float* fm      = (const float*)d_in[0];
    const float* boxes   = (const float*)d_in[1];
    const float* W1a     = (const float*)d_in[2];
    const float* b1a     = (const float*)d_in[3];
    const float* W2a     = (const float*)d_in[4];
    const float* b2a     = (const float*)d_in[5];
    const float* W1b     = (const float*)d_in[6];
    const float* b1b     = (const float*)d_in[7];
    const float* W2b     = (const float*)d_in[8];
    const float* b2b     = (const float*)d_in[9];
    const float* W1c     = (const float*)d_in[10];
    const float* b1c     = (const float*)d_in[11];
    const float* W2c     = (const float*)d_in[12];
    const float* b2c     = (const float*)d_in[13];
    const float* scale_w = (const float*)d_in[14];
    const float* Wg      = (const float*)d_in[15];
    const float* bg      = (const float*)d_in[16];
    float* out = (float*)d_out;

    // launches 1..5 prep, #6 = unified head (ncu -s 5 -c 1 captures it)
    transpose_fm_kernel<<<(HH * WW * CC) / 256, 256>>>(fm);
    transpose_w1_all<<<(FIN_TOT * HID + 255) / 256, 256>>>(W1a, W1b, W1c);
    gf_kernel<<<CC, 256>>>(fm);
    g_kernel<<<1, 16>>>(Wg, bg);
    g_write_kernel<<<(NBOX * 16) / 256, 256>>>(out);

    unified_head_kernel<<<384, 256>>>(boxes,
                                      b1a, W2a, b2a,
                                      b1b, W2b, b2b,
                                      b1c, W2c, b2c,
                                      scale_w, out);
}

// round 4
// speedup vs baseline: 1.3367x; 1.3367x over previous
#include <cuda_runtime.h>
#include <cstdint>

// ---------------- problem constants ----------------
#define CC      64
#define HH      120
#define WW      120
#define NBOX    8192
#define HID     128
#define SCOORD  (119.0f / 960.0f)

#define FIN_A   576
#define FIN_B   3136
#define FIN_C   7744
#define FIN_TOT (FIN_A + FIN_B + FIN_C)

#define NT_A    36          // K-tiles (of 16) per head
#define NT_B    196
#define NT_C    484

#define N_ITEMS 896         // 512 c + 256 b + 128 a

// ---------------- device scratch ----------------
__device__ float d_fmT[HH * WW * CC];            // [y][x][c]
__device__ float d_W1T[FIN_TOT * HID];           // pos-major permuted W1^T
__device__ float d_Hpart[7 * NBOX * HID];        // partial H slabs: c:0-3, b:4-5, a:6
__device__ float d_gf[CC];
__device__ float d_g[16];
__device__ int   d_ctr;

// ---------------- f32x2 / cp.async helpers ----------------
__device__ __forceinline__ unsigned long long pack2(float x) {
    unsigned long long r;
    asm("mov.b64 %0, {%1, %1};" : "=l"(r) : "r"(__float_as_uint(x)));
    return r;
}
__device__ __forceinline__ void fma2(unsigned long long& d,
                                     unsigned long long a,
                                     unsigned long long b) {
    asm("fma.rn.f32x2 %0, %1, %2, %0;" : "+l"(d) : "l"(a), "l"(b));
}
__device__ __forceinline__ uint32_t smem_u32(const void* p) {
    uint32_t a;
    asm("{ .reg .u64 t; cvta.to.shared.u64 t, %1; cvt.u32.u64 %0, t; }" : "=r"(a) : "l"(p));
    return a;
}
__device__ __forceinline__ void cp_async16(uint32_t s, const void* g) {
    asm volatile("cp.async.cg.shared.global [%0], [%1], 16;" :: "r"(s), "l"(g));
}
#define CP_COMMIT()  asm volatile("cp.async.commit_group;")
#define CP_WAIT0()   asm volatile("cp.async.wait_group 0;" ::: "memory")

// ---------------- prep kernels ----------------
__global__ void transpose_fm_kernel(const float* __restrict__ fm) {
    int idx = blockIdx.x * 256 + threadIdx.x;
    if (idx == 0) d_ctr = 0;                      // reset work queue each replay
    int c = idx & 63;
    int p = idx >> 6;
    d_fmT[idx] = fm[c * (HH * WW) + p];
}

__global__ void transpose_w1_all(const float* __restrict__ W1a,
                                 const float* __restrict__ W1b,
                                 const float* __restrict__ W1c) {
    int idx = blockIdx.x * 256 + threadIdx.x;
    const float* W1;
    int fin, r2, base;
    if (idx < FIN_A * HID)                { W1 = W1a; fin = FIN_A; r2 = 9;   base = 0; }
    else if (idx < (FIN_A + FIN_B) * HID) { W1 = W1b; fin = FIN_B; r2 = 49;  base = FIN_A * HID; }
    else if (idx < FIN_TOT * HID)         { W1 = W1c; fin = FIN_C; r2 = 121; base = (FIN_A + FIN_B) * HID; }
    else return;
    int rel = idx - base;
    int n   = rel & 127;
    int kp  = rel >> 7;
    int c   = kp & 63;
    int pos = kp >> 6;
    d_W1T[idx] = W1[n * fin + c * r2 + pos];
}

__global__ void gf_kernel(const float* __restrict__ fm) {
    int c = blockIdx.x;
    float s = 0.0f;
    for (int i = threadIdx.x; i < HH * WW; i += 256) s += fm[c * (HH * WW) + i];
    __shared__ float red[8];
    #pragma unroll
    for (int off = 16; off; off >>= 1) s += __shfl_down_sync(0xffffffffu, s, off);
    if ((threadIdx.x & 31) == 0) red[threadIdx.x >> 5] = s;
    __syncthreads();
    if (threadIdx.x < 8) {
        s = red[threadIdx.x];
        #pragma unroll
        for (int off = 4; off; off >>= 1) s += __shfl_down_sync(0xffu, s, off);
        if (threadIdx.x == 0) d_gf[c] = s / (float)(HH * WW);
    }
}

__global__ void g_kernel(const float* __restrict__ Wg, const float* __restrict__ bg) {
    int j = threadIdx.x;
    float s = bg[j];
    #pragma unroll 8
    for (int c = 0; c < CC; c++) s += d_gf[c] * Wg[j * CC + c];
    d_g[j] = s;
}

__global__ void g_write_kernel(float* __restrict__ out) {
    int idx = blockIdx.x * 256 + threadIdx.x;
    int m = idx >> 4;
    int j = idx & 15;
    out[m * 64 + 48 + j] = d_g[j];
}

// ---------------- persistent layer-1 GEMM kernel ----------------
// Work item = (head, 64-box tile, K-chunk). 256 threads, thread tile 4m x 8n.
// Writes raw partial sums (no bias/relu) to a private slab of d_Hpart.

struct Pref {
    float4 t00, t01, t10, t11;
    float  w00, w01, w10, w11;
};

__device__ __forceinline__ Pref do_prefetch(int kt, int r, float invr,
                                            const float* __restrict__ boxp,
                                            int tid) {
    Pref p;
    int pos = kt >> 2;
    int c0  = (kt & 3) << 4;
    int py  = pos / r;
    int px  = pos - py * r;
    float tx = px * invr;
    float ty = py * invr;

    int m    = tid >> 2;
    int cvec = c0 + ((tid & 3) << 2);

    const float4 bp = *reinterpret_cast<const float4*>(&boxp[m * 4]);
    float ix = fmaf(bp.y, tx, bp.x);
    float iy = fmaf(bp.w, ty, bp.z);
    float x0f = floorf(ix), y0f = floorf(iy);
    float wx = ix - x0f, wy = iy - y0f;
    int x0 = (int)x0f, y0 = (int)y0f;
    int x1 = x0 + 1,   y1 = y0 + 1;
    float vx0 = (x0 >= 0 && x0 < WW) ? 1.0f : 0.0f;
    float vx1 = (x1 >= 0 && x1 < WW) ? 1.0f : 0.0f;
    float vy0 = (y0 >= 0 && y0 < HH) ? 1.0f : 0.0f;
    float vy1 = (y1 >= 0 && y1 < HH) ? 1.0f : 0.0f;
    p.w00 = (1.0f - wx) * (1.0f - wy) * vx0 * vy0;
    p.w01 = wx * (1.0f - wy) * vx1 * vy0;
    p.w10 = (1.0f - wx) * wy * vx0 * vy1;
    p.w11 = wx * wy * vx1 * vy1;
    int cx0 = min(max(x0, 0), WW - 1), cx1 = min(max(x1, 0), WW - 1);
    int cy0 = min(max(y0, 0), HH - 1), cy1 = min(max(y1, 0), HH - 1);

    const float4* f = reinterpret_cast<const float4*>(d_fmT);
    int cq = cvec >> 2;
    p.t00 = __ldg(&f[(cy0 * WW + cx0) * 16 + cq]);
    p.t01 = __ldg(&f[(cy0 * WW + cx1) * 16 + cq]);
    p.t10 = __ldg(&f[(cy1 * WW + cx0) * 16 + cq]);
    p.t11 = __ldg(&f[(cy1 * WW + cx1) * 16 + cq]);
    return p;
}

__global__ void __launch_bounds__(256, 2)
layer1_kernel(const float* __restrict__ boxes) {
    // dbuf: buf0 As[0,1024) Bs[1024,3072); buf1 As[3072,4096) Bs[4096,6144)
    __shared__ float pool[6144];
    __shared__ float boxp[256];
    __shared__ int   s_item;

    const int tid = threadIdx.x;

    const int m0 = (tid >> 4) << 2;   // gemm: 4 boxes
    const int n0 = (tid & 15) << 3;   // gemm: 8 hidden
    const int sm  = tid >> 2;         // im2col: box
    const int skl = (tid & 3) << 2;   // im2col: channel group

    const uint32_t bs_base0 = smem_u32(&pool[1024]) + tid * 16;
    const uint32_t bs_base1 = smem_u32(&pool[4096]) + tid * 16;

    while (true) {
        if (tid == 0) s_item = atomicAdd(&d_ctr, 1);
        __syncthreads();
        const int item = s_item;
        if (item >= N_ITEMS) break;

        // decode item -> (head params, box tile, K-chunk)
        int bt, k0, ktiles, slab, r, w1tbase;
        float invr;
        if (item < 512) {            // head c: 4 chunks of 121
            bt = item >> 2; int ci = item & 3;
            k0 = ci * 121; ktiles = 121; slab = ci;
            r = 11; invr = 0.1f; w1tbase = (FIN_A + FIN_B) * HID;
        } else if (item < 768) {     // head b: 2 chunks of 98
            int rel = item - 512;
            bt = rel >> 1; int ci = rel & 1;
            k0 = ci * 98; ktiles = 98; slab = 4 + ci;
            r = 7; invr = 1.0f / 6.0f; w1tbase = FIN_A * HID;
        } else {                     // head a: 1 chunk of 36
            bt = item - 768;
            k0 = 0; ktiles = 36; slab = 6;
            r = 3; invr = 0.5f; w1tbase = 0;
        }
        const int box0 = bt * 64;

        if (tid < 64) {
            float4 b4 = __ldg(reinterpret_cast<const float4*>(boxes) + (box0 + tid));
            float4 o;
            o.x = b4.x * SCOORD;
            o.y = (b4.z - b4.x) * SCOORD;
            o.z = b4.y * SCOORD;
            o.w = (b4.w - b4.y) * SCOORD;
            *reinterpret_cast<float4*>(&boxp[tid * 4]) = o;
        }
        __syncthreads();

        const float* w1t = d_W1T + w1tbase;

        unsigned long long acc[4][4];
        #pragma unroll
        for (int i = 0; i < 4; i++)
            #pragma unroll
            for (int j = 0; j < 4; j++) acc[i][j] = 0ull;

        // prologue: B(k0) via cp.async, A(k0) taps to regs
        {
            const float* src = w1t + (size_t)k0 * 2048 + tid * 4;
            cp_async16(bs_base0,        src);
            cp_async16(bs_base0 + 4096, src + 1024);
        }
        CP_COMMIT();
        Pref p = do_prefetch(k0, r, invr, boxp, tid);

        for (int t = 0; t < ktiles; ++t) {
            float* As = pool + (t & 1) * 3072;
            const float* Bs = As + 1024;

            {
                float4 v;
                v.x = p.w00 * p.t00.x + p.w01 * p.t01.x + p.w10 * p.t10.x + p.w11 * p.t11.x;
                v.y = p.w00 * p.t00.y + p.w01 * p.t01.y + p.w10 * p.t10.y + p.w11 * p.t11.y;
                v.z = p.w00 * p.t00.z + p.w01 * p.t01.z + p.w10 * p.t10.z + p.w11 * p.t11.z;
                v.w = p.w00 * p.t00.w + p.w01 * p.t01.w + p.w10 * p.t10.w + p.w11 * p.t11.w;
                As[(skl + 0) * 64 + sm] = v.x;
                As[(skl + 1) * 64 + sm] = v.y;
                As[(skl + 2) * 64 + sm] = v.z;
                As[(skl + 3) * 64 + sm] = v.w;
            }

            if (t + 1 < ktiles) p = do_prefetch(k0 + t + 1, r, invr, boxp, tid);

            CP_WAIT0();
            __syncthreads();

            if (t + 1 < ktiles) {
                uint32_t dstb = ((t + 1) & 1) ? bs_base1 : bs_base0;
                const float* src = w1t + (size_t)(k0 + t + 1) * 2048 + tid * 4;
                cp_async16(dstb,        src);
                cp_async16(dstb + 4096, src + 1024);
            }
            CP_COMMIT();

            #pragma unroll
            for (int k = 0; k < 16; k++) {
                float4 av = *reinterpret_cast<const float4*>(&As[k * 64 + m0]);
                ulonglong2 bv0 = *reinterpret_cast<const ulonglong2*>(&Bs[k * 128 + n0]);
                ulonglong2 bv1 = *reinterpret_cast<const ulonglong2*>(&Bs[k * 128 + n0 + 4]);
                unsigned long long a;
                a = pack2(av.x);
                fma2(acc[0][0], a, bv0.x); fma2(acc[0][1], a, bv0.y);
                fma2(acc[0][2], a, bv1.x); fma2(acc[0][3], a, bv1.y);
                a = pack2(av.y);
                fma2(acc[1][0], a, bv0.x); fma2(acc[1][1], a, bv0.y);
                fma2(acc[1][2], a, bv1.x); fma2(acc[1][3], a, bv1.y);
                a = pack2(av.z);
                fma2(acc[2][0], a, bv0.x); fma2(acc[2][1], a, bv0.y);
                fma2(acc[2][2], a, bv1.x); fma2(acc[2][3], a, bv1.y);
                a = pack2(av.w);
                fma2(acc[3][0], a, bv0.x); fma2(acc[3][1], a, bv0.y);
                fma2(acc[3][2], a, bv1.x); fma2(acc[3][3], a, bv1.y);
            }
            __syncthreads();
        }

        // write raw partial sums to slab
        float* slabp = d_Hpart + (size_t)slab * (NBOX * HID) + (size_t)box0 * HID;
        #pragma unroll
        for (int i = 0; i < 4; i++) {
            #pragma unroll
            for (int j = 0; j < 4; j++) {
                *reinterpret_cast<unsigned long long*>(
                    &slabp[(m0 + i) * HID + n0 + 2 * j]) = acc[i][j];
            }
        }
        __syncthreads();   // protect s_item / boxp for next item
    }
}

// ---------------- finisher: sum slabs, bias+relu, layer-2 ----------------
__global__ void __launch_bounds__(256, 2)
finisher_kernel(const float* __restrict__ b1a, const float* __restrict__ W2a,
                const float* __restrict__ b2a,
                const float* __restrict__ b1b, const float* __restrict__ W2b,
                const float* __restrict__ b2b,
                const float* __restrict__ b1c, const float* __restrict__ W2c,
                const float* __restrict__ b2c,
                const float* __restrict__ scale_w,
                float* __restrict__ out) {
    __shared__ float Hs[8192];      // 64 boxes x 128
    const int tid  = threadIdx.x;
    const int box0 = blockIdx.x * 64;

    #pragma unroll
    for (int h = 0; h < 3; h++) {
        const float *b1, *W2, *b2;
        int slab0, nslab, od, col0, swi;
        if (h == 0)      { b1 = b1a; W2 = W2a; b2 = b2a; slab0 = 6; nslab = 1; od = 22; col0 = 0;  swi = 0; }
        else if (h == 1) { b1 = b1b; W2 = W2b; b2 = b2b; slab0 = 4; nslab = 2; od = 21; col0 = 22; swi = 1; }
        else             { b1 = b1c; W2 = W2c; b2 = b2c; slab0 = 0; nslab = 4; od = 5;  col0 = 43; swi = 2; }

        // sum slabs + bias + relu -> Hs
        const size_t gbase = (size_t)box0 * HID;
        for (int i = tid * 4; i < 8192; i += 1024) {
            float4 s = *reinterpret_cast<const float4*>(
                &d_Hpart[(size_t)slab0 * (NBOX * HID) + gbase + i]);
            for (int q = 1; q < nslab; q++) {
                float4 t = *reinterpret_cast<const float4*>(
                    &d_Hpart[(size_t)(slab0 + q) * (NBOX * HID) + gbase + i]);
                s.x += t.x; s.y += t.y; s.z += t.z; s.w += t.w;
            }
            int n = i & 127;
            float4 bb = *reinterpret_cast<const float4*>(&b1[n]);
            s.x = fmaxf(s.x + bb.x, 0.0f);
            s.y = fmaxf(s.y + bb.y, 0.0f);
            s.z = fmaxf(s.z + bb.z, 0.0f);
            s.w = fmaxf(s.w + bb.w, 0.0f);
            *reinterpret_cast<float4*>(&Hs[i]) = s;
        }
        __syncthreads();

        // layer-2
        const float sw = __ldg(&scale_w[swi]);
        const int njobs = od << 6;
        for (int job = tid; job < njobs; job += 256) {
            int mm = job / od;
            int o  = job - mm * od;
            float s = __ldg(&b2[o]);
            const float4* hrow = reinterpret_cast<const float4*>(&Hs[mm * 128]);
            const float4* wrow = reinterpret_cast<const float4*>(&W2[o * 128]);
            #pragma unroll 8
            for (int qq = 0; qq < 32; qq++) {
                float4 h4 = hrow[qq];
                float4 w4 = __ldg(&wrow[qq]);
                s += h4.x * w4.x + h4.y * w4.y + h4.z * w4.z + h4.w * w4.w;
            }
            out[(size_t)(box0 + mm) * 64 + col0 + o] = fmaxf(s, 0.0f) * sw;
        }
        __syncthreads();
    }
}

// ---------------- launch ----------------
extern "C" void kernel_launch(void* const* d_in, const int* in_sizes, int n_in,
                              void* d_out, int out_size) {
    const float* fm      = (const float*)d_in[0];
    const float* boxes   = (const float*)d_in[1];
    const float* W1a     = (const float*)d_in[2];
    const float* b1a     = (const float*)d_in[3];
    const float* W2a     = (const float*)d_in[4];
    const float* b2a     = (const float*)d_in[5];
    const float* W1b     = (const float*)d_in[6];
    const float* b1b     = (const float*)d_in[7];
    const float* W2b     = (const float*)d_in[8];
    const float* b2b     = (const float*)d_in[9];
    const float* W1c     = (const float*)d_in[10];
    const float* b1c     = (const float*)d_in[11];
    const float* W2c     = (const float*)d_in[12];
    const float* b2c     = (const float*)d_in[13];
    const float* scale_w = (const float*)d_in[14];
    const float* Wg      = (const float*)d_in[15];
    const float* bg      = (const float*)d_in[16];
    float* out = (float*)d_out;

    // launches 1..5 prep, #6 = layer1 (ncu -s 5 -c 1 captures it), #7 finisher
    transpose_fm_kernel<<<(HH * WW * CC) / 256, 256>>>(fm);
    transpose_w1_all<<<(FIN_TOT * HID + 255) / 256, 256>>>(W1a, W1b, W1c);
    gf_kernel<<<CC, 256>>>(fm);
    g_kernel<<<1, 16>>>(Wg, bg);
    g_write_kernel<<<(NBOX * 16) / 256, 256>>>(out);

    layer1_kernel<<<304, 256>>>(boxes);

    finisher_kernel<<<NBOX / 64, 256>>>(b1a, W2a, b2a,
                                        b1b, W2b, b2b,
                                        b1c, W2c, b2c,
                                        scale_w, out);
}

// round 6
// speedup vs baseline: 2.3603x; 1.7658x over previous
#include <cuda_runtime.h>
#include <cuda_bf16.h>
#include <cstdint>

// ---------------- problem constants ----------------
#define CC      64
#define HH      120
#define WW      120
#define NBOX    8192
#define HID     128
#define SCOORD  (119.0f / 960.0f)

#define FIN_A   576
#define FIN_B   3136
#define FIN_C   7744

// k-tile = 16 real k. head tiles: A 36, B 196, C 484 -> 716 total
#define T_A0    0
#define T_B0    36
#define T_C0    232
#define NTILES  716
#define N_ITEMS 1024        // c: 11 chunks x 64 box-tiles, b: 4 x 64, a: 1 x 64
#define NSLAB   16          // c: 0-10, b: 11-14, a: 15

// per-tile B image: 2 images x 128 n-rows x 80B (64B data + 16B pad) = 20480B
#define BTILE_BYTES 20480
#define BTILE_WORDS 5120

// smem map (dynamic): boxp 2048 | A bufs 2x10240 | B bufs 2x20480
#define SM_BOXP 0
#define SM_A    2048
#define SM_B    22528
#define SM_TOT  63488

// ---------------- device scratch ----------------
__device__ float    d_fmT[HH * WW * CC];            // [y][x][c]
__device__ uint32_t d_Wbf[NTILES * BTILE_WORDS];    // padded bf16 dup images
__device__ float    d_Hpart[NSLAB * NBOX * HID];    // partial H slabs
__device__ float    d_gf[CC];
__device__ float    d_g[16];
__device__ int      d_ctr;

// ---------------- helpers ----------------
__device__ __forceinline__ uint32_t smem_u32(const void* p) {
    uint32_t a;
    asm("{ .reg .u64 t; cvta.to.shared.u64 t, %1; cvt.u32.u64 %0, t; }" : "=r"(a) : "l"(p));
    return a;
}
__device__ __forceinline__ void cp_async16(uint32_t s, const void* g) {
    asm volatile("cp.async.cg.shared.global [%0], [%1], 16;" :: "r"(s), "l"(g));
}
#define CP_COMMIT()  asm volatile("cp.async.commit_group;")
#define CP_WAIT0()   asm volatile("cp.async.wait_group 0;" ::: "memory")

__device__ __forceinline__ void ldsm4(uint32_t* r, uint32_t addr) {
    asm volatile("ldmatrix.sync.aligned.m8n8.x4.shared.b16 {%0,%1,%2,%3}, [%4];"
                 : "=r"(r[0]), "=r"(r[1]), "=r"(r[2]), "=r"(r[3]) : "r"(addr));
}
__device__ __forceinline__ void hmma(float* c, const uint32_t* a,
                                     uint32_t b0, uint32_t b1) {
    asm volatile("mma.sync.aligned.m16n8k16.row.col.f32.bf16.bf16.f32 "
                 "{%0,%1,%2,%3}, {%4,%5,%6,%7}, {%8,%9}, {%0,%1,%2,%3};"
                 : "+f"(c[0]), "+f"(c[1]), "+f"(c[2]), "+f"(c[3])
                 : "r"(a[0]), "r"(a[1]), "r"(a[2]), "r"(a[3]), "r"(b0), "r"(b1));
}
__device__ __forceinline__ uint32_t packhl(float x) {   // (lo<<16)|hi bf16 pair
    __nv_bfloat16 h = __float2bfloat16(x);
    __nv_bfloat16 l = __float2bfloat16(x - __bfloat162float(h));
    return ((uint32_t)__bfloat16_as_ushort(l) << 16) | (uint32_t)__bfloat16_as_ushort(h);
}

// ---------------- prep kernels ----------------
__global__ void transpose_fm_kernel(const float* __restrict__ fm) {
    int idx = blockIdx.x * 256 + threadIdx.x;
    if (idx == 0) d_ctr = 0;
    int c = idx & 63;
    int p = idx >> 6;
    d_fmT[idx] = fm[c * (HH * WW) + p];
}

// build padded dup bf16 B images: word (tg, img, n, j) at tg*5120 + img*2560 + n*20 + j
__global__ void wbf_prep_kernel(const float* __restrict__ W1a,
                                const float* __restrict__ W1b,
                                const float* __restrict__ W1c) {
    int idx = blockIdx.x * 256 + threadIdx.x;     // over 716*128*16
    if (idx >= NTILES * 2048) return;
    int tg  = idx >> 11;
    int rem = idx & 2047;
    int n = rem >> 4;
    int j = rem & 15;
    const float* W; int fin, r2, tr;
    if (tg < T_B0)      { W = W1a; fin = FIN_A; r2 = 9;   tr = tg; }
    else if (tg < T_C0) { W = W1b; fin = FIN_B; r2 = 49;  tr = tg - T_B0; }
    else                { W = W1c; fin = FIN_C; r2 = 121; tr = tg - T_C0; }
    int kr  = tr * 16 + j;
    int pos = kr >> 6;
    int c   = kr & 63;
    float v = W[n * fin + c * r2 + pos];
    __nv_bfloat16 h = __float2bfloat16(v);
    __nv_bfloat16 l = __float2bfloat16(v - __bfloat162float(h));
    uint32_t hb = (uint32_t)__bfloat16_as_ushort(h);
    uint32_t lb = (uint32_t)__bfloat16_as_ushort(l);
    d_Wbf[tg * BTILE_WORDS + n * 20 + j]        = (hb << 16) | hb;
    d_Wbf[tg * BTILE_WORDS + 2560 + n * 20 + j] = (lb << 16) | lb;
}

__global__ void gf_kernel(const float* __restrict__ fm) {
    int c = blockIdx.x;
    float s = 0.0f;
    for (int i = threadIdx.x; i < HH * WW; i += 256) s += fm[c * (HH * WW) + i];
    __shared__ float red[8];
    #pragma unroll
    for (int off = 16; off; off >>= 1) s += __shfl_down_sync(0xffffffffu, s, off);
    if ((threadIdx.x & 31) == 0) red[threadIdx.x >> 5] = s;
    __syncthreads();
    if (threadIdx.x < 8) {
        s = red[threadIdx.x];
        #pragma unroll
        for (int off = 4; off; off >>= 1) s += __shfl_down_sync(0xffu, s, off);
        if (threadIdx.x == 0) d_gf[c] = s / (float)(HH * WW);
    }
}

__global__ void g_kernel(const float* __restrict__ Wg, const float* __restrict__ bg) {
    int j = threadIdx.x;
    float s = bg[j];
    #pragma unroll 8
    for (int c = 0; c < CC; c++) s += d_gf[c] * Wg[j * CC + c];
    d_g[j] = s;
}

__global__ void g_write_kernel(float* __restrict__ out) {
    int idx = blockIdx.x * 256 + threadIdx.x;
    int m = idx >> 4;
    int j = idx & 15;
    out[m * 64 + 48 + j] = d_g[j];
}

// ---------------- persistent HMMA layer-1 kernel ----------------
// item = (head, 128-box tile, K-chunk). 256 threads = 8 warps (2m x 4n).
// Warp tile 64m x 32n, mma.sync m16n8k16 bf16, fp32 register accumulators.

struct Pref {
    float4 t00a, t00b, t01a, t01b, t10a, t10b, t11a, t11b;
    float  w00, w01, w10, w11;
};

__device__ __forceinline__ Pref do_prefetch(int tr, int r, float invr,
                                            const float4 bp, int half) {
    Pref p;
    int pos = tr >> 2;
    int py  = pos / r;
    int px  = pos - py * r;
    float tx = px * invr;
    float ty = py * invr;
    float ix = fmaf(bp.y, tx, bp.x);
    float iy = fmaf(bp.w, ty, bp.z);
    float x0f = floorf(ix), y0f = floorf(iy);
    float wx = ix - x0f, wy = iy - y0f;
    int x0 = (int)x0f, y0 = (int)y0f;
    int x1 = x0 + 1,   y1 = y0 + 1;
    float vx0 = (x0 >= 0 && x0 < WW) ? 1.0f : 0.0f;
    float vx1 = (x1 >= 0 && x1 < WW) ? 1.0f : 0.0f;
    float vy0 = (y0 >= 0 && y0 < HH) ? 1.0f : 0.0f;
    float vy1 = (y1 >= 0 && y1 < HH) ? 1.0f : 0.0f;
    p.w00 = (1.0f - wx) * (1.0f - wy) * vx0 * vy0;
    p.w01 = wx * (1.0f - wy) * vx1 * vy0;
    p.w10 = (1.0f - wx) * wy * vx0 * vy1;
    p.w11 = wx * wy * vx1 * vy1;
    int cx0 = min(max(x0, 0), WW - 1), cx1 = min(max(x1, 0), WW - 1);
    int cy0 = min(max(y0, 0), HH - 1), cy1 = min(max(y1, 0), HH - 1);

    const float4* f = reinterpret_cast<const float4*>(d_fmT);
    const int cb4 = ((tr & 3) << 2) + (half << 1);   // float4 index of c0
    const int b00 = (cy0 * WW + cx0) * 16 + cb4;
    const int b01 = (cy0 * WW + cx1) * 16 + cb4;
    const int b10 = (cy1 * WW + cx0) * 16 + cb4;
    const int b11 = (cy1 * WW + cx1) * 16 + cb4;
    p.t00a = __ldg(&f[b00]); p.t00b = __ldg(&f[b00 + 1]);
    p.t01a = __ldg(&f[b01]); p.t01b = __ldg(&f[b01 + 1]);
    p.t10a = __ldg(&f[b10]); p.t10b = __ldg(&f[b10 + 1]);
    p.t11a = __ldg(&f[b11]); p.t11b = __ldg(&f[b11 + 1]);
    return p;
}

__global__ void __launch_bounds__(256, 1)
layer1_kernel(const float* __restrict__ boxes) {
    extern __shared__ char smem[];
    const uint32_t sb = smem_u32(smem);
    float* boxp = (float*)(smem + SM_BOXP);
    __shared__ int s_item;

    const int tid  = threadIdx.x;
    const int wid  = tid >> 5;
    const int lane = tid & 31;
    const int wm   = wid & 1;          // m half of CTA tile
    const int wn   = wid >> 1;         // n quarter
    // ldmatrix lane offset within a 16x16 fragment (80B row stride)
    const uint32_t laneOff = (uint32_t)(((lane & 7) + ((lane >> 3) & 1) * 8) * 80
                                        + (lane >> 4) * 16);
    const int m    = tid >> 1;         // im2col: box row
    const int half = tid & 1;          // im2col: 8-channel half

    while (true) {
        if (tid == 0) s_item = atomicAdd(&d_ctr, 1);
        __syncthreads();
        const int item = s_item;
        if (item >= N_ITEMS) break;

        // decode: items grouped by K-chunk for L2 reuse of B tiles
        int bt, t0, nt, slab, r, headT0;
        float invr;
        if (item < 704) {                 // head c: 11 chunks of 44
            int ci = item >> 6; bt = item & 63;
            t0 = T_C0 + ci * 44; nt = 44; slab = ci;
            r = 11; invr = 0.1f; headT0 = T_C0;
        } else if (item < 960) {          // head b: 4 chunks of 49
            int rel = item - 704;
            int ci = rel >> 6; bt = rel & 63;
            t0 = T_B0 + ci * 49; nt = 49; slab = 11 + ci;
            r = 7; invr = 1.0f / 6.0f; headT0 = T_B0;
        } else {                          // head a: 1 chunk of 36
            bt = item - 960;
            t0 = T_A0; nt = 36; slab = 15;
            r = 3; invr = 0.5f; headT0 = T_A0;
        }
        const int box0 = bt * 128;

        if (tid < 128) {
            float4 b4 = __ldg(reinterpret_cast<const float4*>(boxes) + (box0 + tid));
            float4 o;
            o.x = b4.x * SCOORD;
            o.y = (b4.z - b4.x) * SCOORD;
            o.z = b4.y * SCOORD;
            o.w = (b4.w - b4.y) * SCOORD;
            *reinterpret_cast<float4*>(&boxp[tid * 4]) = o;
        }
        __syncthreads();

        const float4 bp = *reinterpret_cast<const float4*>(&boxp[m * 4]);

        float acc[4][4][4];
        #pragma unroll
        for (int i = 0; i < 4; i++)
            #pragma unroll
            for (int j = 0; j < 4; j++)
                #pragma unroll
                for (int q = 0; q < 4; q++) acc[i][j][q] = 0.0f;

        // prologue: cp.async B(t0) into buf0; prefetch taps(t0)
        {
            const char* src = (const char*)d_Wbf + (size_t)t0 * BTILE_BYTES + tid * 16;
            uint32_t dst = sb + SM_B + tid * 16;
            #pragma unroll
            for (int i = 0; i < 5; i++) cp_async16(dst + i * 4096, src + i * 4096);
        }
        CP_COMMIT();
        Pref p = do_prefetch(t0 - headT0, r, invr, bp, half);

        for (int t = 0; t < nt; ++t) {
            const int buf = t & 1;
            const uint32_t aBase = sb + SM_A + buf * 10240;
            const uint32_t bBase = sb + SM_B + buf * 20480;

            // A tile: combine taps, hi/lo split, STS.128 (words j..j+3)
            {
                uint32_t rowOff = (uint32_t)(m * 80 + half * 32);
                float4 v;
                uint4 wv;
                v.x = p.w00 * p.t00a.x + p.w01 * p.t01a.x + p.w10 * p.t10a.x + p.w11 * p.t11a.x;
                v.y = p.w00 * p.t00a.y + p.w01 * p.t01a.y + p.w10 * p.t10a.y + p.w11 * p.t11a.y;
                v.z = p.w00 * p.t00a.z + p.w01 * p.t01a.z + p.w10 * p.t10a.z + p.w11 * p.t11a.z;
                v.w = p.w00 * p.t00a.w + p.w01 * p.t01a.w + p.w10 * p.t10a.w + p.w11 * p.t11a.w;
                wv.x = packhl(v.x); wv.y = packhl(v.y); wv.z = packhl(v.z); wv.w = packhl(v.w);
                *(uint4*)(smem + SM_A + buf * 10240 + rowOff) = wv;
                v.x = p.w00 * p.t00b.x + p.w01 * p.t01b.x + p.w10 * p.t10b.x + p.w11 * p.t11b.x;
                v.y = p.w00 * p.t00b.y + p.w01 * p.t01b.y + p.w10 * p.t10b.y + p.w11 * p.t11b.y;
                v.z = p.w00 * p.t00b.z + p.w01 * p.t01b.z + p.w10 * p.t10b.z + p.w11 * p.t11b.z;
                v.w = p.w00 * p.t00b.w + p.w01 * p.t01b.w + p.w10 * p.t10b.w + p.w11 * p.t11b.w;
                wv.x = packhl(v.x); wv.y = packhl(v.y); wv.z = packhl(v.z); wv.w = packhl(v.w);
                *(uint4*)(smem + SM_A + buf * 10240 + rowOff + 16) = wv;
            }

            if (t + 1 < nt) p = do_prefetch(t0 + t + 1 - headT0, r, invr, bp, half);

            CP_WAIT0();           // B(t) landed (this thread's chunks)
            __syncthreads();      // all A stores + all B chunks visible

            if (t + 1 < nt) {     // B(t+1) into other buf (its last reader finished pre-barrier)
                const char* src = (const char*)d_Wbf
                                + (size_t)(t0 + t + 1) * BTILE_BYTES + tid * 16;
                uint32_t dst = sb + SM_B + ((t + 1) & 1) * 20480 + tid * 16;
                #pragma unroll
                for (int i = 0; i < 5; i++) cp_async16(dst + i * 4096, src + i * 4096);
            }
            CP_COMMIT();

            // MMA: 2 k16 steps x 2 images x (4 mf x 4 nf)
            const uint32_t aB = aBase + (uint32_t)(wm * 5120);
            const uint32_t bB = bBase + (uint32_t)(wn * 2560);
            #pragma unroll
            for (int s = 0; s < 2; s++) {
                uint32_t af[4][4];
                #pragma unroll
                for (int mf = 0; mf < 4; mf++)
                    ldsm4(af[mf], aB + mf * 1280 + s * 32 + laneOff);
                #pragma unroll
                for (int img = 0; img < 2; img++) {
                    uint32_t b0[4], b1[4];
                    uint32_t bb = bB + img * 10240 + s * 32 + laneOff;
                    ldsm4(b0, bb);
                    ldsm4(b1, bb + 1280);
                    #pragma unroll
                    for (int mf = 0; mf < 4; mf++) {
                        hmma(acc[mf][0], af[mf], b0[0], b0[2]);
                        hmma(acc[mf][1], af[mf], b0[1], b0[3]);
                        hmma(acc[mf][2], af[mf], b1[0], b1[2]);
                        hmma(acc[mf][3], af[mf], b1[1], b1[3]);
                    }
                }
            }
            __syncthreads();      // reads of buf done before overwrite
        }

        // epilogue: write partial sums to slab
        {
            float* slabp = d_Hpart + (size_t)slab * (NBOX * HID) + (size_t)box0 * HID;
            const int rb = wm * 64 + (lane >> 2);
            const int cb = wn * 32 + (lane & 3) * 2;
            #pragma unroll
            for (int mf = 0; mf < 4; mf++) {
                #pragma unroll
                for (int nf = 0; nf < 4; nf++) {
                    int rr = rb + mf * 16;
                    int cc = cb + nf * 8;
                    float2 v0 = make_float2(acc[mf][nf][0], acc[mf][nf][1]);
                    float2 v1 = make_float2(acc[mf][nf][2], acc[mf][nf][3]);
                    *reinterpret_cast<float2*>(&slabp[rr * HID + cc])       = v0;
                    *reinterpret_cast<float2*>(&slabp[(rr + 8) * HID + cc]) = v1;
                }
            }
        }
    }
}

// ---------------- finisher: sum slabs, bias+relu, layer-2 ----------------
__global__ void __launch_bounds__(256, 2)
finisher_kernel(const float* __restrict__ b1a, const float* __restrict__ W2a,
                const float* __restrict__ b2a,
                const float* __restrict__ b1b, const float* __restrict__ W2b,
                const float* __restrict__ b2b,
                const float* __restrict__ b1c, const float* __restrict__ W2c,
                const float* __restrict__ b2c,
                const float* __restrict__ scale_w,
                float* __restrict__ out) {
    __shared__ float Hs[8192];      // 64 boxes x 128
    const int tid  = threadIdx.x;
    const int box0 = blockIdx.x * 64;

    #pragma unroll
    for (int h = 0; h < 3; h++) {
        const float *b1, *W2, *b2;
        int slab0, nslab, od, col0, swi;
        if (h == 0)      { b1 = b1a; W2 = W2a; b2 = b2a; slab0 = 15; nslab = 1;  od = 22; col0 = 0;  swi = 0; }
        else if (h == 1) { b1 = b1b; W2 = W2b; b2 = b2b; slab0 = 11; nslab = 4;  od = 21; col0 = 22; swi = 1; }
        else             { b1 = b1c; W2 = W2c; b2 = b2c; slab0 = 0;  nslab = 11; od = 5;  col0 = 43; swi = 2; }

        const size_t gbase = (size_t)box0 * HID;
        for (int i = tid * 4; i < 8192; i += 1024) {
            float4 s = *reinterpret_cast<const float4*>(
                &d_Hpart[(size_t)slab0 * (NBOX * HID) + gbase + i]);
            for (int q = 1; q < nslab; q++) {
                float4 t = *reinterpret_cast<const float4*>(
                    &d_Hpart[(size_t)(slab0 + q) * (NBOX * HID) + gbase + i]);
                s.x += t.x; s.y += t.y; s.z += t.z; s.w += t.w;
            }
            int n = i & 127;
            float4 bb = *reinterpret_cast<const float4*>(&b1[n]);
            s.x = fmaxf(s.x + bb.x, 0.0f);
            s.y = fmaxf(s.y + bb.y, 0.0f);
            s.z = fmaxf(s.z + bb.z, 0.0f);
            s.w = fmaxf(s.w + bb.w, 0.0f);
            *reinterpret_cast<float4*>(&Hs[i]) = s;
        }
        __syncthreads();

        const float sw = __ldg(&scale_w[swi]);
        const int njobs = od << 6;
        for (int job = tid; job < njobs; job += 256) {
            int mm = job / od;
            int o  = job - mm * od;
            float s = __ldg(&b2[o]);
            const float4* hrow = reinterpret_cast<const float4*>(&Hs[mm * 128]);
            const float4* wrow = reinterpret_cast<const float4*>(&W2[o * 128]);
            #pragma unroll 8
            for (int qq = 0; qq < 32; qq++) {
                float4 h4 = hrow[qq];
                float4 w4 = __ldg(&wrow[qq]);
                s += h4.x * w4.x + h4.y * w4.y + h4.z * w4.z + h4.w * w4.w;
            }
            out[(size_t)(box0 + mm) * 64 + col0 + o] = fmaxf(s, 0.0f) * sw;
        }
        __syncthreads();
    }
}

// ---------------- launch ----------------
extern "C" void kernel_launch(void* const* d_in, const int* in_sizes, int n_in,
                              void* d_out, int out_size) {
    const float* fm      = (const float*)d_in[0];
    const float* boxes   = (const float*)d_in[1];
    const float* W1a     = (const float*)d_in[2];
    const float* b1a     = (const float*)d_in[3];
    const float* W2a     = (const float*)d_in[4];
    const float* b2a     = (const float*)d_in[5];
    const float* W1b     = (const float*)d_in[6];
    const float* b1b     = (const float*)d_in[7];
    const float* W2b     = (const float*)d_in[8];
    const float* b2b     = (const float*)d_in[9];
    const float* W1c     = (const float*)d_in[10];
    const float* b1c     = (const float*)d_in[11];
    const float* W2c     = (const float*)d_in[12];
    const float* b2c     = (const float*)d_in[13];
    const float* scale_w = (const float*)d_in[14];
    const float* Wg      = (const float*)d_in[15];
    const float* bg      = (const float*)d_in[16];
    float* out = (float*)d_out;

    cudaFuncSetAttribute(layer1_kernel,
                         cudaFuncAttributeMaxDynamicSharedMemorySize, SM_TOT);

    // launches 1..5 prep, #6 = layer1 (ncu -s 5 -c 1 target), #7 finisher
    transpose_fm_kernel<<<(HH * WW * CC) / 256, 256>>>(fm);
    wbf_prep_kernel<<<(NTILES * 2048 + 255) / 256, 256>>>(W1a, W1b, W1c);
    gf_kernel<<<CC, 256>>>(fm);
    g_kernel<<<1, 16>>>(Wg, bg);
    g_write_kernel<<<(NBOX * 16) / 256, 256>>>(out);

    layer1_kernel<<<148, 256, SM_TOT>>>(boxes);

    finisher_kernel<<<NBOX / 64, 256>>>(b1a, W2a, b2a,
                                        b1b, W2b, b2b,
                                        b1c, W2c, b2c,
                                        scale_w, out);
}

// round 7
// speedup vs baseline: 3.0734x; 1.3021x over previous
#include <cuda_runtime.h>
#include <cuda_bf16.h>
#include <cstdint>

// ---------------- problem constants ----------------
#define CC      64
#define HH      120
#define WW      120
#define NBOX    8192
#define HID     128
#define SCOORD  (119.0f / 960.0f)

#define FIN_A   576
#define FIN_B   3136
#define FIN_C   7744

// k-tile = 16 real k. head tiles: A 36, B 196, C 484 -> 716 total
#define T_A0    0
#define T_B0    36
#define T_C0    232
#define NTILES  716
#define N_ITEMS 1024        // c: 11 chunks x 64 box-tiles, b: 4 x 64, a: 1 x 64
#define NSLAB   16          // c: 0-10, b: 11-14, a: 15

// ---------------- device scratch ----------------
__device__ float    d_fmT[HH * WW * CC];            // [y][x][c]
__device__ uint32_t d_Wp[NTILES * 2048];            // fragment-linear packed (hi,lo) B
__device__ float    d_Hpart[NSLAB * NBOX * HID];    // partial H slabs
__device__ float    d_gf[CC];
__device__ int      d_ctr;

// ---------------- helpers ----------------
__device__ __forceinline__ void ldsm4(uint32_t* r, uint32_t addr) {
    asm volatile("ldmatrix.sync.aligned.m8n8.x4.shared.b16 {%0,%1,%2,%3}, [%4];"
                 : "=r"(r[0]), "=r"(r[1]), "=r"(r[2]), "=r"(r[3]) : "r"(addr));
}
__device__ __forceinline__ void hmma(float* c, const uint32_t* a,
                                     uint32_t b0, uint32_t b1) {
    asm volatile("mma.sync.aligned.m16n8k16.row.col.f32.bf16.bf16.f32 "
                 "{%0,%1,%2,%3}, {%4,%5,%6,%7}, {%8,%9}, {%0,%1,%2,%3};"
                 : "+f"(c[0]), "+f"(c[1]), "+f"(c[2]), "+f"(c[3])
                 : "r"(a[0]), "r"(a[1]), "r"(a[2]), "r"(a[3]), "r"(b0), "r"(b1));
}
__device__ __forceinline__ uint32_t prmt(uint32_t a, uint32_t sel) {
    uint32_t d;
    asm("prmt.b32 %0, %1, %1, %2;" : "=r"(d) : "r"(a), "r"(sel));
    return d;
}
__device__ __forceinline__ uint32_t packhl(float x) {   // (lo<<16)|hi bf16 pair
    __nv_bfloat16 h = __float2bfloat16(x);
    __nv_bfloat16 l = __float2bfloat16(x - __bfloat162float(h));
    return ((uint32_t)__bfloat16_as_ushort(l) << 16) | (uint32_t)__bfloat16_as_ushort(h);
}
__device__ __forceinline__ uint32_t smem_u32(const void* p) {
    uint32_t a;
    asm("{ .reg .u64 t; cvta.to.shared.u64 t, %1; cvt.u32.u64 %0, t; }" : "=r"(a) : "l"(p));
    return a;
}

// ---------------- prep kernels ----------------
__global__ void transpose_fm_kernel(const float* __restrict__ fm) {
    int idx = blockIdx.x * 256 + threadIdx.x;
    if (idx == 0) d_ctr = 0;
    int c = idx & 63;
    int p = idx >> 6;
    d_fmT[idx] = fm[c * (HH * WW) + p];
}

// fragment-linear packed B: word (tg, wn, s, b01, lane, nf) at
//   tg*2048 + (((wn*2+s)*2+b01)*32 + lane)*4 + nf
// content: k = s*8 + b01*4 + (lane&3), n = wn*32 + nf*8 + (lane>>2)
__global__ void wp_prep_kernel(const float* __restrict__ W1a,
                               const float* __restrict__ W1b,
                               const float* __restrict__ W1c) {
    int idx = blockIdx.x * 256 + threadIdx.x;     // over NTILES*2048
    if (idx >= NTILES * 2048) return;
    int tg   = idx >> 11;
    int w    = idx & 2047;
    int nf   = w & 3;
    int lane = (w >> 2) & 31;
    int b01  = (w >> 7) & 1;
    int s    = (w >> 8) & 1;
    int wn   = (w >> 9) & 3;
    int k = s * 8 + b01 * 4 + (lane & 3);
    int n = wn * 32 + nf * 8 + (lane >> 2);
    const float* W; int fin, r2, tr;
    if (tg < T_B0)      { W = W1a; fin = FIN_A; r2 = 9;   tr = tg; }
    else if (tg < T_C0) { W = W1b; fin = FIN_B; r2 = 49;  tr = tg - T_B0; }
    else                { W = W1c; fin = FIN_C; r2 = 121; tr = tg - T_C0; }
    int kr  = tr * 16 + k;
    int pos = kr >> 6;
    int c   = kr & 63;
    d_Wp[idx] = packhl(W[n * fin + c * r2 + pos]);
}

__global__ void gf_kernel(const float* __restrict__ fm) {
    int c = blockIdx.x;
    float s = 0.0f;
    for (int i = threadIdx.x; i < HH * WW; i += 256) s += fm[c * (HH * WW) + i];
    __shared__ float red[8];
    #pragma unroll
    for (int off = 16; off; off >>= 1) s += __shfl_down_sync(0xffffffffu, s, off);
    if ((threadIdx.x & 31) == 0) red[threadIdx.x >> 5] = s;
    __syncthreads();
    if (threadIdx.x < 8) {
        s = red[threadIdx.x];
        #pragma unroll
        for (int off = 4; off; off >>= 1) s += __shfl_down_sync(0xffu, s, off);
        if (threadIdx.x == 0) d_gf[c] = s / (float)(HH * WW);
    }
}

// ---------------- persistent HMMA layer-1 kernel ----------------
// item = (head, 128-box tile, K-chunk). 256 threads = 8 warps (2m x 4n).
// A via smem+ldmatrix (80B-stride rows); B via direct LDG.128 register
// fragments of packed (hi,lo) words, PRMT-expanded at use.

struct Pref {
    float4 t00a, t00b, t01a, t01b, t10a, t10b, t11a, t11b;
    float  w00, w01, w10, w11;
};

__device__ __forceinline__ Pref do_prefetch(int tr, int r, float invr,
                                            const float4 bp, int half) {
    Pref p;
    int pos = tr >> 2;
    int py  = pos / r;
    int px  = pos - py * r;
    float tx = px * invr;
    float ty = py * invr;
    float ix = fmaf(bp.y, tx, bp.x);
    float iy = fmaf(bp.w, ty, bp.z);
    float x0f = floorf(ix), y0f = floorf(iy);
    float wx = ix - x0f, wy = iy - y0f;
    int x0 = (int)x0f, y0 = (int)y0f;
    int x1 = x0 + 1,   y1 = y0 + 1;
    float vx0 = (x0 >= 0 && x0 < WW) ? 1.0f : 0.0f;
    float vx1 = (x1 >= 0 && x1 < WW) ? 1.0f : 0.0f;
    float vy0 = (y0 >= 0 && y0 < HH) ? 1.0f : 0.0f;
    float vy1 = (y1 >= 0 && y1 < HH) ? 1.0f : 0.0f;
    p.w00 = (1.0f - wx) * (1.0f - wy) * vx0 * vy0;
    p.w01 = wx * (1.0f - wy) * vx1 * vy0;
    p.w10 = (1.0f - wx) * wy * vx0 * vy1;
    p.w11 = wx * wy * vx1 * vy1;
    int cx0 = min(max(x0, 0), WW - 1), cx1 = min(max(x1, 0), WW - 1);
    int cy0 = min(max(y0, 0), HH - 1), cy1 = min(max(y1, 0), HH - 1);

    const float4* f = reinterpret_cast<const float4*>(d_fmT);
    const int cb4 = ((tr & 3) << 2) + (half << 1);
    const int b00 = (cy0 * WW + cx0) * 16 + cb4;
    const int b01 = (cy0 * WW + cx1) * 16 + cb4;
    const int b10 = (cy1 * WW + cx0) * 16 + cb4;
    const int b11 = (cy1 * WW + cx1) * 16 + cb4;
    p.t00a = __ldg(&f[b00]); p.t00b = __ldg(&f[b00 + 1]);
    p.t01a = __ldg(&f[b01]); p.t01b = __ldg(&f[b01 + 1]);
    p.t10a = __ldg(&f[b10]); p.t10b = __ldg(&f[b10 + 1]);
    p.t11a = __ldg(&f[b11]); p.t11b = __ldg(&f[b11 + 1]);
    return p;
}

__global__ void __launch_bounds__(256, 1)
layer1_kernel(const float* __restrict__ boxes) {
    // static smem: boxp 2048 | A bufs 2 x 10240
    __shared__ __align__(16) char smem[22528];
    float* boxp = (float*)smem;
    const uint32_t aSm = smem_u32(smem) + 2048;
    __shared__ int s_item;

    const int tid  = threadIdx.x;
    const int wid  = tid >> 5;
    const int lane = tid & 31;
    const int wm   = wid & 1;
    const int wn   = wid >> 1;
    const uint32_t laneOff = (uint32_t)(((lane & 7) + ((lane >> 3) & 1) * 8) * 80
                                        + (lane >> 4) * 16);
    const int m    = tid >> 1;
    const int half = tid & 1;

    while (true) {
        if (tid == 0) s_item = atomicAdd(&d_ctr, 1);
        __syncthreads();
        const int item = s_item;
        if (item >= N_ITEMS) break;

        int bt, t0, nt, slab, r, headT0;
        float invr;
        if (item < 704) {                 // head c: 11 chunks of 44
            int ci = item >> 6; bt = item & 63;
            t0 = T_C0 + ci * 44; nt = 44; slab = ci;
            r = 11; invr = 0.1f; headT0 = T_C0;
        } else if (item < 960) {          // head b: 4 chunks of 49
            int rel = item - 704;
            int ci = rel >> 6; bt = rel & 63;
            t0 = T_B0 + ci * 49; nt = 49; slab = 11 + ci;
            r = 7; invr = 1.0f / 6.0f; headT0 = T_B0;
        } else {                          // head a
            bt = item - 960;
            t0 = T_A0; nt = 36; slab = 15;
            r = 3; invr = 0.5f; headT0 = T_A0;
        }
        const int box0 = bt * 128;

        if (tid < 128) {
            float4 b4 = __ldg(reinterpret_cast<const float4*>(boxes) + (box0 + tid));
            float4 o;
            o.x = b4.x * SCOORD;
            o.y = (b4.z - b4.x) * SCOORD;
            o.z = b4.y * SCOORD;
            o.w = (b4.w - b4.y) * SCOORD;
            *reinterpret_cast<float4*>(&boxp[tid * 4]) = o;
        }
        __syncthreads();

        const float4 bp = *reinterpret_cast<const float4*>(&boxp[m * 4]);

        float acc[4][4][4];
        #pragma unroll
        for (int i = 0; i < 4; i++)
            #pragma unroll
            for (int j = 0; j < 4; j++)
                #pragma unroll
                for (int q = 0; q < 4; q++) acc[i][j][q] = 0.0f;

        // warp's B fragment base for tile t: d_Wp bytes + t*8192 + wn*2048 + lane*16
        const char* wpB = (const char*)d_Wp + (size_t)wn * 2048 + (size_t)lane * 16;

        // prologue: taps(t0), B(t0)
        Pref p = do_prefetch(t0 - headT0, r, invr, bp, half);
        uint4 bq[2][2];   // [s][b01]
        {
            const char* src = wpB + (size_t)t0 * 8192;
            bq[0][0] = *reinterpret_cast<const uint4*>(src);
            bq[0][1] = *reinterpret_cast<const uint4*>(src + 512);
            bq[1][0] = *reinterpret_cast<const uint4*>(src + 1024);
            bq[1][1] = *reinterpret_cast<const uint4*>(src + 1536);
        }

        for (int t = 0; t < nt; ++t) {
            const int buf = t & 1;
            const uint32_t aBase = aSm + buf * 10240;

            // A tile store: combine taps, hi/lo pack, 2x STS.128
            {
                uint32_t rowOff = (uint32_t)(m * 80 + half * 32);
                float4 v; uint4 wv;
                v.x = p.w00 * p.t00a.x + p.w01 * p.t01a.x + p.w10 * p.t10a.x + p.w11 * p.t11a.x;
                v.y = p.w00 * p.t00a.y + p.w01 * p.t01a.y + p.w10 * p.t10a.y + p.w11 * p.t11a.y;
                v.z = p.w00 * p.t00a.z + p.w01 * p.t01a.z + p.w10 * p.t10a.z + p.w11 * p.t11a.z;
                v.w = p.w00 * p.t00a.w + p.w01 * p.t01a.w + p.w10 * p.t10a.w + p.w11 * p.t11a.w;
                wv.x = packhl(v.x); wv.y = packhl(v.y); wv.z = packhl(v.z); wv.w = packhl(v.w);
                *(uint4*)(smem + 2048 + buf * 10240 + rowOff) = wv;
                v.x = p.w00 * p.t00b.x + p.w01 * p.t01b.x + p.w10 * p.t10b.x + p.w11 * p.t11b.x;
                v.y = p.w00 * p.t00b.y + p.w01 * p.t01b.y + p.w10 * p.t10b.y + p.w11 * p.t11b.y;
                v.z = p.w00 * p.t00b.z + p.w01 * p.t01b.z + p.w10 * p.t10b.z + p.w11 * p.t11b.z;
                v.w = p.w00 * p.t00b.w + p.w01 * p.t01b.w + p.w10 * p.t10b.w + p.w11 * p.t11b.w;
                wv.x = packhl(v.x); wv.y = packhl(v.y); wv.z = packhl(v.z); wv.w = packhl(v.w);
                *(uint4*)(smem + 2048 + buf * 10240 + rowOff + 16) = wv;
            }

            // prefetch next tile's taps + B fragments
            uint4 bqn[2][2];
            if (t + 1 < nt) {
                p = do_prefetch(t0 + t + 1 - headT0, r, invr, bp, half);
                const char* src = wpB + (size_t)(t0 + t + 1) * 8192;
                bqn[0][0] = *reinterpret_cast<const uint4*>(src);
                bqn[0][1] = *reinterpret_cast<const uint4*>(src + 512);
                bqn[1][0] = *reinterpret_cast<const uint4*>(src + 1024);
                bqn[1][1] = *reinterpret_cast<const uint4*>(src + 1536);
            }

            __syncthreads();     // A(t) visible; MMA(t-1) reads done before A(t) stores (in-order)

            // MMA: 2 k16 steps x (img expand via PRMT) x 4 mf x 4 nf
            const uint32_t aB = aBase + (uint32_t)(wm * 5120);
            #pragma unroll
            for (int s = 0; s < 2; s++) {
                uint32_t af[4][4];
                #pragma unroll
                for (int mf = 0; mf < 4; mf++)
                    ldsm4(af[mf], aB + mf * 1280 + s * 32 + laneOff);
                const uint32_t* w0 = reinterpret_cast<const uint32_t*>(&bq[s][0]);
                const uint32_t* w1 = reinterpret_cast<const uint32_t*>(&bq[s][1]);
                #pragma unroll
                for (int nf = 0; nf < 4; nf++) {
                    uint32_t b0h = prmt(w0[nf], 0x1010u);
                    uint32_t b1h = prmt(w1[nf], 0x1010u);
                    uint32_t b0l = prmt(w0[nf], 0x3232u);
                    uint32_t b1l = prmt(w1[nf], 0x3232u);
                    #pragma unroll
                    for (int mf = 0; mf < 4; mf++) {
                        hmma(acc[mf][nf], af[mf], b0h, b1h);
                        hmma(acc[mf][nf], af[mf], b0l, b1l);
                    }
                }
            }

            if (t + 1 < nt) {
                bq[0][0] = bqn[0][0]; bq[0][1] = bqn[0][1];
                bq[1][0] = bqn[1][0]; bq[1][1] = bqn[1][1];
            }
        }

        // epilogue: write partial sums to slab
        {
            float* slabp = d_Hpart + (size_t)slab * (NBOX * HID) + (size_t)box0 * HID;
            const int rb = wm * 64 + (lane >> 2);
            const int cb = wn * 32 + (lane & 3) * 2;
            #pragma unroll
            for (int mf = 0; mf < 4; mf++) {
                #pragma unroll
                for (int nf = 0; nf < 4; nf++) {
                    int rr = rb + mf * 16;
                    int cc = cb + nf * 8;
                    *reinterpret_cast<float2*>(&slabp[rr * HID + cc]) =
                        make_float2(acc[mf][nf][0], acc[mf][nf][1]);
                    *reinterpret_cast<float2*>(&slabp[(rr + 8) * HID + cc]) =
                        make_float2(acc[mf][nf][2], acc[mf][nf][3]);
                }
            }
        }
        __syncthreads();   // boxp/s_item safe for next item
    }
}

// ---------------- finisher: slabs -> H -> layer-2; global head inline ----------------
__global__ void __launch_bounds__(256, 2)
finisher_kernel(const float* __restrict__ b1a, const float* __restrict__ W2a,
                const float* __restrict__ b2a,
                const float* __restrict__ b1b, const float* __restrict__ W2b,
                const float* __restrict__ b2b,
                const float* __restrict__ b1c, const float* __restrict__ W2c,
                const float* __restrict__ b2c,
                const float* __restrict__ scale_w,
                const float* __restrict__ Wg, const float* __restrict__ bg,
                float* __restrict__ out) {
    __shared__ float Hs[8192];
    __shared__ float sG[16];
    const int tid  = threadIdx.x;
    const int box0 = blockIdx.x * 64;

    // global head (cheap, per block)
    if (tid < 16) {
        float s = bg[tid];
        #pragma unroll 8
        for (int c = 0; c < CC; c++) s += d_gf[c] * Wg[tid * CC + c];
        sG[tid] = s;
    }
    __syncthreads();
    for (int idx = tid; idx < 1024; idx += 256) {
        int mm = idx >> 4;
        int j  = idx & 15;
        out[(size_t)(box0 + mm) * 64 + 48 + j] = sG[j];
    }

    #pragma unroll
    for (int h = 0; h < 3; h++) {
        const float *b1, *W2, *b2;
        int slab0, nslab, od, col0, swi;
        if (h == 0)      { b1 = b1a; W2 = W2a; b2 = b2a; slab0 = 15; nslab = 1;  od = 22; col0 = 0;  swi = 0; }
        else if (h == 1) { b1 = b1b; W2 = W2b; b2 = b2b; slab0 = 11; nslab = 4;  od = 21; col0 = 22; swi = 1; }
        else             { b1 = b1c; W2 = W2c; b2 = b2c; slab0 = 0;  nslab = 11; od = 5;  col0 = 43; swi = 2; }

        const size_t gbase = (size_t)box0 * HID;
        for (int i = tid * 4; i < 8192; i += 1024) {
            float4 s = *reinterpret_cast<const float4*>(
                &d_Hpart[(size_t)slab0 * (NBOX * HID) + gbase + i]);
            for (int q = 1; q < nslab; q++) {
                float4 t = *reinterpret_cast<const float4*>(
                    &d_Hpart[(size_t)(slab0 + q) * (NBOX * HID) + gbase + i]);
                s.x += t.x; s.y += t.y; s.z += t.z; s.w += t.w;
            }
            int n = i & 127;
            float4 bb = *reinterpret_cast<const float4*>(&b1[n]);
            s.x = fmaxf(s.x + bb.x, 0.0f);
            s.y = fmaxf(s.y + bb.y, 0.0f);
            s.z = fmaxf(s.z + bb.z, 0.0f);
            s.w = fmaxf(s.w + bb.w, 0.0f);
            *reinterpret_cast<float4*>(&Hs[i]) = s;
        }
        __syncthreads();

        const float sw = __ldg(&scale_w[swi]);
        const int njobs = od << 6;
        for (int job = tid; job < njobs; job += 256) {
            int mm = job / od;
            int o  = job - mm * od;
            float s = __ldg(&b2[o]);
            const float4* hrow = reinterpret_cast<const float4*>(&Hs[mm * 128]);
            const float4* wrow = reinterpret_cast<const float4*>(&W2[o * 128]);
            #pragma unroll 8
            for (int qq = 0; qq < 32; qq++) {
                float4 h4 = hrow[qq];
                float4 w4 = __ldg(&wrow[qq]);
                s += h4.x * w4.x + h4.y * w4.y + h4.z * w4.z + h4.w * w4.w;
            }
            out[(size_t)(box0 + mm) * 64 + col0 + o] = fmaxf(s, 0.0f) * sw;
        }
        __syncthreads();
    }
}

// ---------------- launch ----------------
extern "C" void kernel_launch(void* const* d_in, const int* in_sizes, int n_in,
                              void* d_out, int out_size) {
    const float* fm      = (const float*)d_in[0];
    const float* boxes   = (const float*)d_in[1];
    const float* W1a     = (const float*)d_in[2];
    const float* b1a     = (const float*)d_in[3];
    const float* W2a     = (const float*)d_in[4];
    const float* b2a     = (const float*)d_in[5];
    const float* W1b     = (const float*)d_in[6];
    const float* b1b     = (const float*)d_in[7];
    const float* W2b     = (const float*)d_in[8];
    const float* b2b     = (const float*)d_in[9];
    const float* W1c     = (const float*)d_in[10];
    const float* b1c     = (const float*)d_in[11];
    const float* W2c     = (const float*)d_in[12];
    const float* b2c     = (const float*)d_in[13];
    const float* scale_w = (const float*)d_in[14];
    const float* Wg      = (const float*)d_in[15];
    const float* bg      = (const float*)d_in[16];
    float* out = (float*)d_out;

    transpose_fm_kernel<<<(HH * WW * CC) / 256, 256>>>(fm);
    wp_prep_kernel<<<(NTILES * 2048 + 255) / 256, 256>>>(W1a, W1b, W1c);
    gf_kernel<<<CC, 256>>>(fm);

    layer1_kernel<<<148, 256>>>(boxes);

    finisher_kernel<<<NBOX / 64, 256>>>(b1a, W2a, b2a,
                                        b1b, W2b, b2b,
                                        b1c, W2c, b2c,
                                        scale_w, Wg, bg, out);
}